// round 16
// baseline (speedup 1.0000x reference)
#include <cuda_runtime.h>
#include <cstddef>

namespace {

constexpr int B = 8, T = 2048, H = 256, L = 16;
constexpr int S = 8;                    // t-strip per main work item
constexpr int WARPS = 4;                // warp g owns l in [4g, 4g+3]
constexpr int THREADS = WARPS * 32;     // 128
constexpr int STRIPS_PER_B = T / S;     // 256
constexpr int MAIN_ITEMS  = B * STRIPS_PER_B;              // 2048
constexpr int RELAY_T_PER_WARP = 16;
constexpr int RELAY_ITEMS = (B * T) / (WARPS * RELAY_T_PER_WARP);  // 256
constexpr int N_ITEMS = MAIN_ITEMS + RELAY_ITEMS;          // 2304
constexpr int GRID = 1064;              // 7 blocks/SM x 152 SMs persistent

using u64 = unsigned long long;
struct P4 { u64 v[4]; };                // 8 floats as 4 packed f32x2
struct TrueT  { static constexpr bool value = true;  };
struct FalseT { static constexpr bool value = false; };

// ---- packed f32x2 helpers ----
__device__ __forceinline__ u64 fma2(u64 a, u64 b, u64 c) {
  u64 r;
  asm("fma.rn.f32x2 %0, %1, %2, %3;" : "=l"(r) : "l"(a), "l"(b), "l"(c));
  return r;
}
__device__ __forceinline__ u64 add2(u64 a, u64 b) {
  u64 r;
  asm("add.rn.f32x2 %0, %1, %2;" : "=l"(r) : "l"(a), "l"(b));
  return r;
}
// Packed max on halves; mov.b64 pack/unpack are register-pair renames.
__device__ __forceinline__ u64 max2(u64 a, u64 b) {
  float alo, ahi, blo, bhi;
  asm("mov.b64 {%0, %1}, %2;" : "=f"(alo), "=f"(ahi) : "l"(a));
  asm("mov.b64 {%0, %1}, %2;" : "=f"(blo), "=f"(bhi) : "l"(b));
  float rlo = fmaxf(alo, blo);
  float rhi = fmaxf(ahi, bhi);
  u64 r;
  asm("mov.b64 %0, {%1, %2};" : "=l"(r) : "f"(rlo), "f"(rhi));
  return r;
}
__device__ __forceinline__ float collapse(u64 p) {  // lo + hi
  float lo, hi;
  asm("mov.b64 {%0, %1}, %2;" : "=f"(lo), "=f"(hi) : "l"(p));
  return lo + hi;
}

// Load 8 floats of row `row` (lane's H-slice) as 4 packed f32x2.
// CHK=true: zeros when row OOB (reference's zero padding).
template <bool CHK>
__device__ __forceinline__ P4 load_rowp(const float* __restrict__ base, int row, int hbase) {
  P4 r;
  if (!CHK || (unsigned)row < (unsigned)T) {
    const ulonglong2* p = reinterpret_cast<const ulonglong2*>(base + (size_t)row * H + hbase);
    ulonglong2 a = p[0];
    ulonglong2 b = p[1];
    r.v[0] = a.x; r.v[1] = a.y; r.v[2] = b.x; r.v[3] = b.y;
  } else {
    r.v[0] = r.v[1] = r.v[2] = r.v[3] = 0ull;   // == {0.f, 0.f}
  }
  return r;
}

// Interleaved merge: lanes with (lane&s)==0 carry the a-class partial sum,
// lanes with (lane&s)!=0 the b-class. One shfl per merge.
__device__ __forceinline__ float shfl_merge(float a, float b, int s, int lane) {
  const bool hi = (lane & s) != 0;
  float send = hi ? a : b;
  float recv = __shfl_xor_sync(0xffffffffu, send, s);
  return (hi ? b : a) + recv;
}

__global__ __launch_bounds__(THREADS, 7)
void ffm_kernel(const float* __restrict__ logits,
                const float* __restrict__ end_w,
                const float* __restrict__ whole_w,
                const float* __restrict__ relay_w,
                const float* __restrict__ relay_b,
                const float* __restrict__ length_bias,
                float* __restrict__ out,
                float* __restrict__ relay_out) {
  // Lane-private window ring in smem: [warp][slot][j][lane]. Each lane only
  // ever reads what it wrote (same-thread ordering -> NO syncs needed).
  // Lane-major layout: LDS.64 across lanes is the standard 2-phase access.
  __shared__ u64 winsm[WARPS][4][4][32];   // 16 KB
  __shared__ u64 ewsm[4][32];              // 1 KB, written once

  const int g    = threadIdx.x >> 5;
  const int lane = threadIdx.x & 31;
  const int hbase = lane * 8;
  // Writer lanes 0,16,8,24 hold finished sums for l = 4g + idx,
  // idx = bit16 + 2*bit8.
  const int  idx    = ((lane >> 4) & 1) + ((lane >> 3) & 1) * 2;
  const bool writer = (lane & 7) == 0;

  // Item-invariant weights (kept in registers).
  P4 w0 = load_rowp<false>(whole_w + (4 * g + 0) * H, 0, hbase);
  P4 w1 = load_rowp<false>(whole_w + (4 * g + 1) * H, 0, hbase);
  P4 w2 = load_rowp<false>(whole_w + (4 * g + 2) * H, 0, hbase);
  P4 w3 = load_rowp<false>(whole_w + (4 * g + 3) * H, 0, hbase);
  const float bias = length_bias[4 * g + idx];

  // end_w slice shared across warps via smem (written once).
  if (threadIdx.x < 32) {
    P4 ew = load_rowp<false>(end_w, 0, threadIdx.x * 8);
#pragma unroll
    for (int j = 0; j < 4; j++) ewsm[j][threadIdx.x] = ew.v[j];
  }
  __syncthreads();

  // Persistent grid-stride over work items: [0, MAIN_ITEMS) = main strips,
  // [MAIN_ITEMS, N_ITEMS) = relay chunks.
  for (int item = blockIdx.x; item < N_ITEMS; item += GRID) {
    if (item < MAIN_ITEMS) {
      // ---------------- main strip ----------------
      const int b  = item >> 8;              // / STRIPS_PER_B
      const int s0 = (item & 255) << 3;      // % STRIPS_PER_B * S
      const float* lb = logits + (size_t)b * T * H;

      auto body = [&](auto chk_tag) {
        constexpr bool CHK = decltype(chk_tag)::value;

        // Prefill ring slots for rows s0-4g-k, k=1..3 (slot (4-k)&3).
#pragma unroll
        for (int k = 1; k <= 3; k++) {
          P4 pr = load_rowp<CHK>(lb, s0 - 4 * g - k, hbase);
#pragma unroll
          for (int j = 0; j < 4; j++) winsm[g][(4 - k) & 3][j][lane] = pr.v[j];
        }

#pragma unroll
        for (int u = 0; u < S; u++) {
          const int p = u & 3;
          const int r = s0 + u;

          // Newest window row: kept in regs for this step AND stored to ring.
          P4 nrow = load_rowp<CHK>(lb, r - 4 * g, hbase);
#pragma unroll
          for (int j = 0; j < 4; j++) winsm[g][p][j][lane] = nrow.v[j];

          P4 cur;
          if (g == 0) cur = nrow;                       // warp 0: row r-0 IS row r
          else        cur = load_rowp<false>(lb, r, hbase);

          u64 E = 0ull, A0 = 0ull, A1 = 0ull, A2 = 0ull, A3 = 0ull;
#pragma unroll
          for (int j = 0; j < 4; j++) {
            const u64 c = cur.v[j];
            E  = fma2(c, ewsm[j][lane], E);
            A0 = fma2(max2(c, nrow.v[j]),                 w0.v[j], A0);  // l=4g
            A1 = fma2(max2(c, winsm[g][(p + 3) & 3][j][lane]), w1.v[j], A1);
            A2 = fma2(max2(c, winsm[g][(p + 2) & 3][j][lane]), w2.v[j], A2);
            A3 = fma2(max2(c, winsm[g][(p + 1) & 3][j][lane]), w3.v[j], A3);
          }
          // Fold end partial (packed), then collapse halves.
          A0 = add2(A0, E); A1 = add2(A1, E); A2 = add2(A2, E); A3 = add2(A3, E);
          float a0 = collapse(A0);
          float a1 = collapse(A1);
          float a2 = collapse(A2);
          float a3 = collapse(A3);

          // Interleaved 4-value warp reduction: 5 shfl total.
          float x = shfl_merge(a0, a1, 16, lane);
          float y = shfl_merge(a2, a3, 16, lane);
          float z = shfl_merge(x,  y,  8,  lane);
          z += __shfl_xor_sync(0xffffffffu, z, 4);
          z += __shfl_xor_sync(0xffffffffu, z, 2);
          z += __shfl_xor_sync(0xffffffffu, z, 1);

          if (writer)
            out[(size_t)(b * T + r) * L + 4 * g + idx] = z + bias;
        }
      };

      // Min row touched is s0-15 (warp 3 prefill); max row s0+S-1 < T.
      if (s0 >= 16) body(FalseT{});
      else          body(TrueT{});
    } else {
      // ---------------- relay chunk ----------------
      // relay[b,t] = sum_h max(x[b,t,h], x_pad[b,t+L,h]) * relay_w[h] + relay_b
      const int c = item - MAIN_ITEMS;
      const int base_t = c * (WARPS * RELAY_T_PER_WARP) + g * RELAY_T_PER_WARP;
      const int b  = base_t >> 11;           // / T
      const int t0 = base_t & 2047;          // % T
      const float* lb = logits + (size_t)b * T * H;

      P4 rw = load_rowp<false>(relay_w, 0, hbase);
      const float rb = relay_b[0];

#pragma unroll
      for (int k = 0; k < RELAY_T_PER_WARP; k += 2) {
        const int t = t0 + k;
        P4 cur0 = load_rowp<false>(lb, t, hbase);
        P4 cur1 = load_rowp<false>(lb, t + 1, hbase);
        P4 nxt0 = load_rowp<true>(lb, t + L, hbase);
        P4 nxt1 = load_rowp<true>(lb, t + L + 1, hbase);

        u64 R0 = 0ull, R1 = 0ull;
#pragma unroll
        for (int j = 0; j < 4; j++) {
          R0 = fma2(max2(cur0.v[j], nxt0.v[j]), rw.v[j], R0);
          R1 = fma2(max2(cur1.v[j], nxt1.v[j]), rw.v[j], R1);
        }
        float rel0 = collapse(R0), rel1 = collapse(R1);

        float m = shfl_merge(rel0, rel1, 16, lane);  // bit16: 0→t, 1→t+1
        m += __shfl_xor_sync(0xffffffffu, m, 8);
        m += __shfl_xor_sync(0xffffffffu, m, 4);
        m += __shfl_xor_sync(0xffffffffu, m, 2);
        m += __shfl_xor_sync(0xffffffffu, m, 1);
        if ((lane & 15) == 0)
          relay_out[(size_t)b * T + t + (lane >> 4)] = m + rb;
      }
    }
  }
}

}  // namespace

extern "C" void kernel_launch(void* const* d_in, const int* in_sizes, int n_in,
                              void* d_out, int out_size) {
  const float* logits  = (const float*)d_in[0];
  const float* end_w   = (const float*)d_in[1];
  const float* whole_w = (const float*)d_in[2];
  const float* relay_w = (const float*)d_in[3];
  const float* relay_b = (const float*)d_in[4];
  const float* lbias   = (const float*)d_in[5];

  float* out   = (float*)d_out;                // [B, T, L]
  float* relay = out + (size_t)B * T * L;      // [B, T] appended

  ffm_kernel<<<GRID, THREADS>>>(logits, end_w, whole_w, relay_w, relay_b,
                                lbias, out, relay);
}

// round 17
// speedup vs baseline: 2.0587x; 2.0587x over previous
#include <cuda_runtime.h>
#include <cstddef>

namespace {

constexpr int B = 8, T = 2048, H = 256, L = 16;
constexpr int S = 8;                    // t-strip per main work item
constexpr int WARPS = 4;                // warp g owns l in [4g, 4g+3]
constexpr int THREADS = WARPS * 32;     // 128
constexpr int STRIPS_PER_B = T / S;     // 256
constexpr int MAIN_ITEMS  = B * STRIPS_PER_B;              // 2048
constexpr int RELAY_T_PER_WARP = 16;
constexpr int RELAY_ITEMS = (B * T) / (WARPS * RELAY_T_PER_WARP);  // 256
constexpr int N_ITEMS = MAIN_ITEMS + RELAY_ITEMS;          // 2304
constexpr int GRID = 608;               // 4 blocks/SM x 152 SMs persistent

using u64 = unsigned long long;
struct P4 { u64 v[4]; };                // 8 floats as 4 packed f32x2
struct TrueT  { static constexpr bool value = true;  };
struct FalseT { static constexpr bool value = false; };

// ---- packed f32x2 helpers ----
__device__ __forceinline__ u64 fma2(u64 a, u64 b, u64 c) {
  u64 r;
  asm("fma.rn.f32x2 %0, %1, %2, %3;" : "=l"(r) : "l"(a), "l"(b), "l"(c));
  return r;
}
__device__ __forceinline__ u64 add2(u64 a, u64 b) {
  u64 r;
  asm("add.rn.f32x2 %0, %1, %2;" : "=l"(r) : "l"(a), "l"(b));
  return r;
}
// Packed max on halves; mov.b64 pack/unpack are register-pair renames.
__device__ __forceinline__ u64 max2(u64 a, u64 b) {
  float alo, ahi, blo, bhi;
  asm("mov.b64 {%0, %1}, %2;" : "=f"(alo), "=f"(ahi) : "l"(a));
  asm("mov.b64 {%0, %1}, %2;" : "=f"(blo), "=f"(bhi) : "l"(b));
  float rlo = fmaxf(alo, blo);
  float rhi = fmaxf(ahi, bhi);
  u64 r;
  asm("mov.b64 %0, {%1, %2};" : "=l"(r) : "f"(rlo), "f"(rhi));
  return r;
}
__device__ __forceinline__ float collapse(u64 p) {  // lo + hi
  float lo, hi;
  asm("mov.b64 {%0, %1}, %2;" : "=f"(lo), "=f"(hi) : "l"(p));
  return lo + hi;
}

// Load 8 floats of row `row` (lane's H-slice) as 4 packed f32x2.
// CHK=true: zeros when row OOB (reference's zero padding).
template <bool CHK>
__device__ __forceinline__ P4 load_rowp(const float* __restrict__ base, int row, int hbase) {
  P4 r;
  if (!CHK || (unsigned)row < (unsigned)T) {
    const ulonglong2* p = reinterpret_cast<const ulonglong2*>(base + (size_t)row * H + hbase);
    ulonglong2 a = p[0];
    ulonglong2 b = p[1];
    r.v[0] = a.x; r.v[1] = a.y; r.v[2] = b.x; r.v[3] = b.y;
  } else {
    r.v[0] = r.v[1] = r.v[2] = r.v[3] = 0ull;   // == {0.f, 0.f}
  }
  return r;
}

// Interleaved merge: lanes with (lane&s)==0 carry the a-class partial sum,
// lanes with (lane&s)!=0 the b-class. One shfl per merge.
__device__ __forceinline__ float shfl_merge(float a, float b, int s, int lane) {
  const bool hi = (lane & s) != 0;
  float send = hi ? a : b;
  float recv = __shfl_xor_sync(0xffffffffu, send, s);
  return (hi ? b : a) + recv;
}

// Full 4-value interleaved warp reduction: 5 shfl total. Writer lane layout:
// lanes 0,16,8,24 end with finished sums for idx = bit16 + 2*bit8.
__device__ __forceinline__ float reduce4(float a0, float a1, float a2, float a3,
                                         int lane) {
  float x = shfl_merge(a0, a1, 16, lane);
  float y = shfl_merge(a2, a3, 16, lane);
  float z = shfl_merge(x,  y,  8,  lane);
  z += __shfl_xor_sync(0xffffffffu, z, 4);
  z += __shfl_xor_sync(0xffffffffu, z, 2);
  z += __shfl_xor_sync(0xffffffffu, z, 1);
  return z;
}

__global__ __launch_bounds__(THREADS, 4)
void ffm_kernel(const float* __restrict__ logits,
                const float* __restrict__ end_w,
                const float* __restrict__ whole_w,
                const float* __restrict__ relay_w,
                const float* __restrict__ relay_b,
                const float* __restrict__ length_bias,
                float* __restrict__ out,
                float* __restrict__ relay_out) {
  const int g    = threadIdx.x >> 5;
  const int lane = threadIdx.x & 31;
  const int hbase = lane * 8;
  const int  idx    = ((lane >> 4) & 1) + ((lane >> 3) & 1) * 2;
  const bool writer = (lane & 7) == 0;

  // Item-invariant state hoisted out of the persistent loop.
  P4 w0 = load_rowp<false>(whole_w + (4 * g + 0) * H, 0, hbase);
  P4 w1 = load_rowp<false>(whole_w + (4 * g + 1) * H, 0, hbase);
  P4 w2 = load_rowp<false>(whole_w + (4 * g + 2) * H, 0, hbase);
  P4 w3 = load_rowp<false>(whole_w + (4 * g + 3) * H, 0, hbase);
  P4 ew = load_rowp<false>(end_w, 0, hbase);
  const float bias = length_bias[4 * g + idx];

  // Persistent grid-stride over work items: [0, MAIN_ITEMS) = main strips,
  // [MAIN_ITEMS, N_ITEMS) = relay chunks.
  for (int item = blockIdx.x; item < N_ITEMS; item += GRID) {
    if (item < MAIN_ITEMS) {
      // ---------------- main strip ----------------
      const int b  = item >> 8;              // / STRIPS_PER_B
      const int s0 = (item & 255) << 3;      // % STRIPS_PER_B * S
      const float* lb = logits + (size_t)b * T * H;

      auto body = [&](auto chk_tag) {
        constexpr bool CHK = decltype(chk_tag)::value;

        // 4-row circular window. Row (s0 + u - 4g) loaded at step u into
        // slot u&3; at step u (p = u & 3), row r-4g-k lives in slot (p-k)&3.
        P4 Wn[4];
#pragma unroll
        for (int k = 1; k <= 3; k++)
          Wn[(4 - k) & 3] = load_rowp<CHK>(lb, s0 - 4 * g - k, hbase);

        // Software-pipelined reduction: step u reduces/stores step u-1's
        // accumulators, so the serial 5-shfl chain overlaps step u's
        // independent loads + math instead of stalling the warp.
        float p0, p1, p2, p3;

#pragma unroll
        for (int u = 0; u < S; u++) {
          const int p = u & 3;
          const int r = s0 + u;

          Wn[p] = load_rowp<CHK>(lb, r - 4 * g, hbase);  // advance window
          P4 cur;
          if (g == 0) cur = Wn[p];                       // warp 0: window row IS row r
          else        cur = load_rowp<false>(lb, r, hbase);

          // Reduce the PREVIOUS step's accs here: the chain interleaves with
          // this step's load latency and math below.
          if (u > 0) {
            float z = reduce4(p0, p1, p2, p3, lane);
            if (writer)
              out[(size_t)(b * T + (r - 1)) * L + 4 * g + idx] = z + bias;
          }

          u64 E = 0ull, A0 = 0ull, A1 = 0ull, A2 = 0ull, A3 = 0ull;
#pragma unroll
          for (int j = 0; j < 4; j++) {
            const u64 c = cur.v[j];
            E  = fma2(c, ew.v[j], E);
            A0 = fma2(max2(c, Wn[p].v[j]),           w0.v[j], A0);  // l = 4g
            A1 = fma2(max2(c, Wn[(p + 3) & 3].v[j]), w1.v[j], A1);  // l = 4g+1
            A2 = fma2(max2(c, Wn[(p + 2) & 3].v[j]), w2.v[j], A2);  // l = 4g+2
            A3 = fma2(max2(c, Wn[(p + 1) & 3].v[j]), w3.v[j], A3);  // l = 4g+3
          }
          // Fold end partial (packed), collapse halves, save for next step.
          A0 = add2(A0, E); A1 = add2(A1, E); A2 = add2(A2, E); A3 = add2(A3, E);
          p0 = collapse(A0);
          p1 = collapse(A1);
          p2 = collapse(A2);
          p3 = collapse(A3);
        }

        // Epilogue: reduce/store the final step.
        {
          float z = reduce4(p0, p1, p2, p3, lane);
          if (writer)
            out[(size_t)(b * T + (s0 + S - 1)) * L + 4 * g + idx] = z + bias;
        }
      };

      // Min row touched is s0-15 (warp 3 prefill); max row s0+S-1 < T.
      if (s0 >= 16) body(FalseT{});
      else          body(TrueT{});
    } else {
      // ---------------- relay chunk ----------------
      // relay[b,t] = sum_h max(x[b,t,h], x_pad[b,t+L,h]) * relay_w[h] + relay_b
      const int c = item - MAIN_ITEMS;
      const int base_t = c * (WARPS * RELAY_T_PER_WARP) + g * RELAY_T_PER_WARP;
      const int b  = base_t >> 11;           // / T
      const int t0 = base_t & 2047;          // % T
      const float* lb = logits + (size_t)b * T * H;

      P4 rw = load_rowp<false>(relay_w, 0, hbase);
      const float rb = relay_b[0];

      // Pipelined by one pair-iteration, same rationale as the main path.
      float q0, q1;
      int   qt = 0;

#pragma unroll
      for (int k = 0; k < RELAY_T_PER_WARP; k += 2) {
        const int t = t0 + k;
        P4 cur0 = load_rowp<false>(lb, t, hbase);
        P4 cur1 = load_rowp<false>(lb, t + 1, hbase);
        P4 nxt0 = load_rowp<true>(lb, t + L, hbase);
        P4 nxt1 = load_rowp<true>(lb, t + L + 1, hbase);

        if (k > 0) {  // reduce previous pair while this pair's loads fly
          float m = shfl_merge(q0, q1, 16, lane);
          m += __shfl_xor_sync(0xffffffffu, m, 8);
          m += __shfl_xor_sync(0xffffffffu, m, 4);
          m += __shfl_xor_sync(0xffffffffu, m, 2);
          m += __shfl_xor_sync(0xffffffffu, m, 1);
          if ((lane & 15) == 0)
            relay_out[(size_t)b * T + qt + (lane >> 4)] = m + rb;
        }

        u64 R0 = 0ull, R1 = 0ull;
#pragma unroll
        for (int j = 0; j < 4; j++) {
          R0 = fma2(max2(cur0.v[j], nxt0.v[j]), rw.v[j], R0);
          R1 = fma2(max2(cur1.v[j], nxt1.v[j]), rw.v[j], R1);
        }
        q0 = collapse(R0);
        q1 = collapse(R1);
        qt = t;
      }

      {  // epilogue pair
        float m = shfl_merge(q0, q1, 16, lane);
        m += __shfl_xor_sync(0xffffffffu, m, 8);
        m += __shfl_xor_sync(0xffffffffu, m, 4);
        m += __shfl_xor_sync(0xffffffffu, m, 2);
        m += __shfl_xor_sync(0xffffffffu, m, 1);
        if ((lane & 15) == 0)
          relay_out[(size_t)b * T + qt + (lane >> 4)] = m + rb;
      }
    }
  }
}

}  // namespace

extern "C" void kernel_launch(void* const* d_in, const int* in_sizes, int n_in,
                              void* d_out, int out_size) {
  const float* logits  = (const float*)d_in[0];
  const float* end_w   = (const float*)d_in[1];
  const float* whole_w = (const float*)d_in[2];
  const float* relay_w = (const float*)d_in[3];
  const float* relay_b = (const float*)d_in[4];
  const float* lbias   = (const float*)d_in[5];

  float* out   = (float*)d_out;                // [B, T, L]
  float* relay = out + (size_t)B * T * L;      // [B, T] appended

  ffm_kernel<<<GRID, THREADS>>>(logits, end_w, whole_w, relay_w, relay_b,
                                lbias, out, relay);
}